// round 7
// baseline (speedup 1.0000x reference)
#include <cuda_runtime.h>
#include <cstdint>

// ============================================================================
// TF32 mma.sync GEMM: out[32768,512] = X @ W^T + bias.
// R2 skeleton (BM=BN=128, BK=32, 2-stage, 8 warps, warp tile 32x64, m16n8k8)
// + column-permuted smem so fragment loads are LDS.128 (24/warp/chunk vs 96
//   scalar). Permutation: within each 16-col K-group, col c -> (c&3)*4+(c>>2).
// Staged via 4B cp.async.ca (coalesced global, conflict-free smem).
// SSTRIDE=48 floats: v4 fragment loads are bank-conflict-free.
// Prefetch issued AFTER __syncthreads (fixes R2 stage-overwrite race).
// ============================================================================

#define MTOT 32768
#define KTOT 512
#define NTOT 512
#define BM   128
#define BN   128
#define BK   32
#define NKC  (KTOT / BK)     // 16
#define THREADS 256
#define SS   48              // smem floats per row (32 data + 16 pad)

#define TILE_FLOATS (128 * SS)     // 6144 floats per operand stage

__device__ __forceinline__ uint32_t smem_u32(const void* p) {
    return (uint32_t)__cvta_generic_to_shared(p);
}

__device__ __forceinline__ uint32_t tf32rn(float x) {
    uint32_t y;
    asm("cvt.rna.tf32.f32 %0, %1;" : "=r"(y) : "f"(x));
    return y;
}

#define CP_ASYNC4(dst_u32, src_ptr)                                           \
    asm volatile("cp.async.ca.shared.global [%0], [%1], 4;"                   \
                 :: "r"(dst_u32), "l"(src_ptr))
#define CP_COMMIT() asm volatile("cp.async.commit_group;" ::: "memory")
#define CP_WAIT(N)  asm volatile("cp.async.wait_group %0;" :: "n"(N) : "memory")

__device__ __forceinline__ void mma_tf32(float* d, const uint32_t* a,
                                         const uint32_t* b) {
    asm volatile(
        "mma.sync.aligned.m16n8k8.row.col.f32.tf32.tf32.f32 "
        "{%0,%1,%2,%3}, {%4,%5,%6,%7}, {%8,%9}, {%0,%1,%2,%3};"
        : "+f"(d[0]), "+f"(d[1]), "+f"(d[2]), "+f"(d[3])
        : "r"(a[0]), "r"(a[1]), "r"(a[2]), "r"(a[3]), "r"(b[0]), "r"(b[1]));
}

__global__ void __launch_bounds__(THREADS, 2)
linear_tf32_kernel(const float* __restrict__ X, const float* __restrict__ W,
                   const float* __restrict__ bias, float* __restrict__ out) {
    extern __shared__ float smem[];
    float* As = smem;                       // [2][TILE_FLOATS]
    float* Bs = smem + 2 * TILE_FLOATS;     // [2][TILE_FLOATS]
    float* bias_s = smem + 4 * TILE_FLOATS; // [BN]

    const int tid = threadIdx.x;
    const int wid = tid >> 5;
    const int lid = tid & 31;
    const int g = lid >> 2;          // group id (0..7)
    const int t = lid & 3;           // thread-in-group (0..3)
    const int wm = (wid & 3) * 32;   // warp M offset
    const int wn = (wid >> 2) * 64;  // warp N offset

    const int n0 = blockIdx.x * BN;
    const int m0 = blockIdx.y * BM;

    const float* Ag = X + (size_t)m0 * KTOT;
    const float* Bg = W + (size_t)n0 * KTOT;

    if (tid < BN) bias_s[tid] = bias[n0 + tid];

    const uint32_t as_b = smem_u32(As);
    const uint32_t bs_b = smem_u32(Bs);

    // Staging: per thread 16 elements of A + 16 of B per chunk.
    // Warp-instr i covers one full smem row: row = wid + 8i, col = lid.
    // Permuted dest column within the row (group-of-16 preserved):
    const int pcol = ((lid & 3) << 2) | ((lid >> 2) & 3) | (lid & 16);

    // -------- prologue: stage chunk 0 --------
    {
        #pragma unroll
        for (int i = 0; i < 16; i++) {
            const int row = wid + 8 * i;
            CP_ASYNC4(as_b + (row * SS + pcol) * 4, Ag + (size_t)row * KTOT + lid);
        }
        #pragma unroll
        for (int i = 0; i < 16; i++) {
            const int row = wid + 8 * i;
            CP_ASYNC4(bs_b + (row * SS + pcol) * 4, Bg + (size_t)row * KTOT + lid);
        }
        CP_COMMIT();
    }

    float acc[2][8][4];
    #pragma unroll
    for (int mi = 0; mi < 2; mi++)
        #pragma unroll
        for (int nj = 0; nj < 8; nj++)
            #pragma unroll
            for (int e = 0; e < 4; e++) acc[mi][nj][e] = 0.0f;

    for (int kc = 0; kc < NKC; kc++) {
        const int s = kc & 1;

        CP_WAIT(0);         // chunk kc landed
        __syncthreads();    // all warps done reading stage s^1 (chunk kc-1)

        // Prefetch chunk kc+1 into stage s^1 (safe: drained by the barrier).
        if (kc + 1 < NKC) {
            const int kb = (kc + 1) * BK;
            const uint32_t an = as_b + (s ^ 1) * TILE_FLOATS * 4;
            const uint32_t bn = bs_b + (s ^ 1) * TILE_FLOATS * 4;
            #pragma unroll
            for (int i = 0; i < 16; i++) {
                const int row = wid + 8 * i;
                CP_ASYNC4(an + (row * SS + pcol) * 4,
                          Ag + (size_t)row * KTOT + kb + lid);
            }
            #pragma unroll
            for (int i = 0; i < 16; i++) {
                const int row = wid + 8 * i;
                CP_ASYNC4(bn + (row * SS + pcol) * 4,
                          Bg + (size_t)row * KTOT + kb + lid);
            }
            CP_COMMIT();
        }

        const float* At = As + s * TILE_FLOATS;
        const float* Bt = Bs + s * TILE_FLOATS;

        #pragma unroll
        for (int G = 0; G < 2; G++) {   // two 16-K groups per chunk
            const int go = G * 16 + 4 * t;

            // A fragments for both K=8 slices of this group: 4 x LDS.128
            uint32_t af0[2][4], af1[2][4];
            #pragma unroll
            for (int mi = 0; mi < 2; mi++) {
                const int r = wm + mi * 16 + g;
                const float4 v  = *reinterpret_cast<const float4*>(At + r * SS + go);
                const float4 v8 = *reinterpret_cast<const float4*>(At + (r + 8) * SS + go);
                af0[mi][0] = tf32rn(v.x);  af0[mi][1] = tf32rn(v8.x);
                af0[mi][2] = tf32rn(v.y);  af0[mi][3] = tf32rn(v8.y);
                af1[mi][0] = tf32rn(v.z);  af1[mi][1] = tf32rn(v8.z);
                af1[mi][2] = tf32rn(v.w);  af1[mi][3] = tf32rn(v8.w);
            }

            #pragma unroll
            for (int h = 0; h < 2; h++) {   // B in two nj-halves (reg pressure)
                uint32_t bf0[4][2], bf1[4][2];
                #pragma unroll
                for (int j = 0; j < 4; j++) {
                    const int n = wn + (h * 4 + j) * 8 + g;
                    const float4 v = *reinterpret_cast<const float4*>(Bt + n * SS + go);
                    bf0[j][0] = tf32rn(v.x);  bf0[j][1] = tf32rn(v.y);
                    bf1[j][0] = tf32rn(v.z);  bf1[j][1] = tf32rn(v.w);
                }
                #pragma unroll
                for (int mi = 0; mi < 2; mi++)
                    #pragma unroll
                    for (int j = 0; j < 4; j++)
                        mma_tf32(acc[mi][h * 4 + j], af0[mi], bf0[j]);
                #pragma unroll
                for (int mi = 0; mi < 2; mi++)
                    #pragma unroll
                    for (int j = 0; j < 4; j++)
                        mma_tf32(acc[mi][h * 4 + j], af1[mi], bf1[j]);
            }
        }
    }

    // -------- epilogue: add bias, store float2 --------
    #pragma unroll
    for (int mi = 0; mi < 2; mi++) {
        const int r0 = m0 + wm + mi * 16 + g;
        #pragma unroll
        for (int nj = 0; nj < 8; nj++) {
            const int cl = wn + nj * 8 + 2 * t;
            const float bx = bias_s[cl];
            const float by = bias_s[cl + 1];
            float2 v0 = make_float2(acc[mi][nj][0] + bx, acc[mi][nj][1] + by);
            float2 v1 = make_float2(acc[mi][nj][2] + bx, acc[mi][nj][3] + by);
            *reinterpret_cast<float2*>(out + (size_t)r0 * NTOT + n0 + cl) = v0;
            *reinterpret_cast<float2*>(out + (size_t)(r0 + 8) * NTOT + n0 + cl) = v1;
        }
    }
}

#define SMEM_BYTES ((4 * TILE_FLOATS + BN) * 4)

extern "C" void kernel_launch(void* const* d_in, const int* in_sizes, int n_in,
                              void* d_out, int out_size) {
    const float* X    = (const float*)d_in[0];
    const float* Wt   = (const float*)d_in[1];
    const float* bias = (const float*)d_in[2];
    float* out = (float*)d_out;

    const int Mrows = in_sizes[0] / KTOT;   // 32768

    cudaFuncSetAttribute(linear_tf32_kernel,
                         cudaFuncAttributeMaxDynamicSharedMemorySize, SMEM_BYTES);

    dim3 grid(NTOT / BN, Mrows / BM);  // (4, 256)
    linear_tf32_kernel<<<grid, THREADS, SMEM_BYTES>>>(X, Wt, bias, out);
}

// round 8
// speedup vs baseline: 1.4391x; 1.4391x over previous
#include <cuda_runtime.h>
#include <cstdint>

// ============================================================================
// TF32 mma.sync GEMM: out[32768,512] = X @ W^T + bias.
// R2 skeleton (BM=BN=128, BK=32, 2-stage, 8 warps, warp tile 32x64, m16n8k8).
// NEW: pre-kernel writes Wperm = tf32-rounded, column-permuted W into 1MB
// __device__ scratch. B fragments then load as LDS.128 with ZERO cvt;
// B staging stays plain 16B cp.async (permutation already in gmem).
// A path unchanged from R2 (scalar LDS + cvt.rna).
// ============================================================================

#define MTOT 32768
#define KTOT 512
#define NTOT 512
#define BM   128
#define BN   128
#define BK   32
#define NKC  (KTOT / BK)     // 16
#define THREADS 256
#define SSA  36              // A smem floats/row (32 data + 4 pad) — scalar LDS
#define SSB  48              // B smem floats/row (32 data + 16 pad) — v4 LDS

#define A_TILE (BM * SSA)    // 4608 floats
#define B_TILE (BN * SSB)    // 6144 floats

__device__ float Wperm[NTOT * KTOT];   // 1MB scratch: tf32-rounded, permuted

__device__ __forceinline__ uint32_t smem_u32(const void* p) {
    return (uint32_t)__cvta_generic_to_shared(p);
}

__device__ __forceinline__ uint32_t tf32rn(float x) {
    uint32_t y;
    asm("cvt.rna.tf32.f32 %0, %1;" : "=r"(y) : "f"(x));
    return y;
}

#define CP_ASYNC_CG(dst_u32, src_ptr)                                         \
    asm volatile("cp.async.cg.shared.global [%0], [%1], 16;"                  \
                 :: "r"(dst_u32), "l"(src_ptr))
#define CP_COMMIT() asm volatile("cp.async.commit_group;" ::: "memory")
#define CP_WAIT(N)  asm volatile("cp.async.wait_group %0;" :: "n"(N) : "memory")

__device__ __forceinline__ void mma_tf32(float* d, const uint32_t* a,
                                         const uint32_t* b) {
    asm volatile(
        "mma.sync.aligned.m16n8k8.row.col.f32.tf32.tf32.f32 "
        "{%0,%1,%2,%3}, {%4,%5,%6,%7}, {%8,%9}, {%0,%1,%2,%3};"
        : "+f"(d[0]), "+f"(d[1]), "+f"(d[2]), "+f"(d[3])
        : "r"(a[0]), "r"(a[1]), "r"(a[2]), "r"(a[3]), "r"(b[0]), "r"(b[1]));
}

// Pre-kernel: Wperm[n][p(k)] = tf32_round(W[n][k]),
// p(k) = (k & ~15) | ((k & 3) << 2) | ((k >> 2) & 3)
__global__ void wprep_kernel(const float* __restrict__ W) {
    const int n = blockIdx.x;
    for (int c = threadIdx.x; c < KTOT; c += blockDim.x) {
        const uint32_t bits = tf32rn(W[n * KTOT + c]);
        const int p = (c & ~15) | ((c & 3) << 2) | ((c >> 2) & 3);
        Wperm[n * KTOT + p] = __uint_as_float(bits);
    }
}

__global__ void __launch_bounds__(THREADS, 2)
linear_tf32_kernel(const float* __restrict__ X, const float* __restrict__ bias,
                   float* __restrict__ out) {
    extern __shared__ float smem[];
    float* As = smem;                           // [2][A_TILE]
    float* Bs = smem + 2 * A_TILE;              // [2][B_TILE]
    float* bias_s = smem + 2 * A_TILE + 2 * B_TILE; // [BN]

    const int tid = threadIdx.x;
    const int wid = tid >> 5;
    const int lid = tid & 31;
    const int g = lid >> 2;          // group id (0..7)
    const int t = lid & 3;           // thread-in-group (0..3)
    const int wm = (wid & 3) * 32;   // warp M offset
    const int wn = (wid >> 2) * 64;  // warp N offset

    const int n0 = blockIdx.x * BN;
    const int m0 = blockIdx.y * BM;

    const float* Ag = X + (size_t)m0 * KTOT;
    const float* Bg = Wperm + (size_t)n0 * KTOT;

    if (tid < BN) bias_s[tid] = bias[n0 + tid];

    const uint32_t as_b = smem_u32(As);
    const uint32_t bs_b = smem_u32(Bs);

    // Staging (R2 scheme): idx in [0,1024): row = idx>>3, ch = idx&7 (16B).
    const int sr0 = tid >> 3;              // rows for the 4 A / 4 B chunks
    const int sch = (tid & 7) * 4;         // float offset within row

    // -------- prologue: stage chunk 0 --------
    {
        #pragma unroll
        for (int i = 0; i < 4; i++) {
            const int row = sr0 + i * 32;
            CP_ASYNC_CG(as_b + (row * SSA + sch) * 4, Ag + (size_t)row * KTOT + sch);
        }
        #pragma unroll
        for (int i = 0; i < 4; i++) {
            const int row = sr0 + i * 32;
            CP_ASYNC_CG(bs_b + (row * SSB + sch) * 4, Bg + (size_t)row * KTOT + sch);
        }
        CP_COMMIT();
    }

    float acc[2][8][4];
    #pragma unroll
    for (int mi = 0; mi < 2; mi++)
        #pragma unroll
        for (int nj = 0; nj < 8; nj++)
            #pragma unroll
            for (int e = 0; e < 4; e++) acc[mi][nj][e] = 0.0f;

    for (int kc = 0; kc < NKC; kc++) {
        const int s = kc & 1;

        CP_WAIT(0);         // chunk kc landed
        __syncthreads();    // stage s^1 fully drained by all warps

        // Prefetch chunk kc+1 into stage s^1 (safe: after barrier).
        if (kc + 1 < NKC) {
            const int kb = (kc + 1) * BK;
            const uint32_t an = as_b + (s ^ 1) * A_TILE * 4;
            const uint32_t bn = bs_b + (s ^ 1) * B_TILE * 4;
            #pragma unroll
            for (int i = 0; i < 4; i++) {
                const int row = sr0 + i * 32;
                CP_ASYNC_CG(an + (row * SSA + sch) * 4,
                            Ag + (size_t)row * KTOT + kb + sch);
            }
            #pragma unroll
            for (int i = 0; i < 4; i++) {
                const int row = sr0 + i * 32;
                CP_ASYNC_CG(bn + (row * SSB + sch) * 4,
                            Bg + (size_t)row * KTOT + kb + sch);
            }
            CP_COMMIT();
        }

        const float* At = As + s * A_TILE;
        const float* Bt = Bs + s * B_TILE;

        #pragma unroll
        for (int G = 0; G < 2; G++) {   // two 16-K groups per chunk
            // B fragments for both K=8 slices of this group:
            // one LDS.128 per nj, zero cvt (pre-rounded, pre-permuted).
            uint32_t bf0[8][2], bf1[8][2];
            #pragma unroll
            for (int nj = 0; nj < 8; nj++) {
                const int n = wn + nj * 8 + g;
                const float4 v = *reinterpret_cast<const float4*>(
                    Bt + n * SSB + G * 16 + 4 * t);
                bf0[nj][0] = __float_as_uint(v.x);
                bf0[nj][1] = __float_as_uint(v.y);
                bf1[nj][0] = __float_as_uint(v.z);
                bf1[nj][1] = __float_as_uint(v.w);
            }
            #pragma unroll
            for (int ks = 0; ks < 2; ks++) {   // K=8 slices within group
                const int k = G * 16 + ks * 8;
                uint32_t af[2][4];
                #pragma unroll
                for (int mi = 0; mi < 2; mi++) {
                    const int r = wm + mi * 16 + g;
                    af[mi][0] = tf32rn(At[r * SSA + k + t]);
                    af[mi][1] = tf32rn(At[(r + 8) * SSA + k + t]);
                    af[mi][2] = tf32rn(At[r * SSA + k + t + 4]);
                    af[mi][3] = tf32rn(At[(r + 8) * SSA + k + t + 4]);
                }
                #pragma unroll
                for (int mi = 0; mi < 2; mi++)
                    #pragma unroll
                    for (int nj = 0; nj < 8; nj++)
                        mma_tf32(acc[mi][nj], af[mi],
                                 ks ? bf1[nj] : bf0[nj]);
            }
        }
    }

    // -------- epilogue: add bias, store float2 --------
    // NOTE: smem column permutation only reorders K (contraction) — output
    // layout is untouched.
    #pragma unroll
    for (int mi = 0; mi < 2; mi++) {
        const int r0 = m0 + wm + mi * 16 + g;
        #pragma unroll
        for (int nj = 0; nj < 8; nj++) {
            const int cl = wn + nj * 8 + 2 * t;
            const float bx = bias_s[cl];
            const float by = bias_s[cl + 1];
            float2 v0 = make_float2(acc[mi][nj][0] + bx, acc[mi][nj][1] + by);
            float2 v1 = make_float2(acc[mi][nj][2] + bx, acc[mi][nj][3] + by);
            *reinterpret_cast<float2*>(out + (size_t)r0 * NTOT + n0 + cl) = v0;
            *reinterpret_cast<float2*>(out + (size_t)(r0 + 8) * NTOT + n0 + cl) = v1;
        }
    }
}

#define SMEM_BYTES ((2 * A_TILE + 2 * B_TILE + BN) * 4)

extern "C" void kernel_launch(void* const* d_in, const int* in_sizes, int n_in,
                              void* d_out, int out_size) {
    const float* X    = (const float*)d_in[0];
    const float* Wt   = (const float*)d_in[1];
    const float* bias = (const float*)d_in[2];
    float* out = (float*)d_out;

    const int Mrows = in_sizes[0] / KTOT;   // 32768

    wprep_kernel<<<NTOT, 256>>>(Wt);

    cudaFuncSetAttribute(linear_tf32_kernel,
                         cudaFuncAttributeMaxDynamicSharedMemorySize, SMEM_BYTES);

    dim3 grid(NTOT / BN, Mrows / BM);  // (4, 256)
    linear_tf32_kernel<<<grid, THREADS, SMEM_BYTES>>>(X, bias, out);
}